// round 2
// baseline (speedup 1.0000x reference)
#include <cuda_runtime.h>
#include <math.h>

#define D 64
#define NF 3
#define MAXU 100000
#define MAXENT 200000
#define MAXE 500000

// ---------------- scratch (device globals; no allocation allowed) ----------------
// tables: Pu [U*D], Pi [ENT*D], Qu [U*D], Qi [ENT*D]
__device__ float g_tab[(size_t)(MAXU + MAXENT) * 2 * D];                 // 38.4M floats
// accumulators: s1 [U*3*D], u2 [U*3*D], ysum [ENT*D], y2 [ENT*D], cnt [U*3], cnti [ENT]
__device__ float g_acc[(size_t)MAXU * NF * D * 2 + (size_t)MAXENT * D * 2
                       + (size_t)MAXU * NF + MAXENT];                     // 64.5M floats
__device__ unsigned char g_rtype[MAXE];

// ---------------- K0: node-level precompute of the 4 half-GEMMs ----------------
// role 0: Pu = user_emb   @ WW_w[:, :64].T
// role 1: Pi = entity_emb @ WW_w[:, 64:].T
// role 2: Qu = user_emb   @ WWi_w[:, 64:].T
// role 3: Qi = entity_emb @ WWi_w[:, :64].T
__global__ __launch_bounds__(64) void precompute_kernel(
    const float* __restrict__ user_emb, const float* __restrict__ entity_emb,
    const float* __restrict__ WW_w, const float* __restrict__ WWi_w,
    float* __restrict__ Pu, float* __restrict__ Pi,
    float* __restrict__ Qu, float* __restrict__ Qi,
    int U, int ENT)
{
    int role = blockIdx.y;
    int d = threadIdx.x;  // 0..63
    const float* W; const float* src; float* dst; int rows;
    if (role == 0)      { W = WW_w;          src = user_emb;   dst = Pu; rows = U;   }
    else if (role == 1) { W = WW_w + D;      src = entity_emb; dst = Pi; rows = ENT; }
    else if (role == 2) { W = WWi_w + D;     src = user_emb;   dst = Qu; rows = U;   }
    else                { W = WWi_w;         src = entity_emb; dst = Qi; rows = ENT; }

    float wreg[D];
    #pragma unroll
    for (int k = 0; k < D; k++) wreg[k] = W[(size_t)d * 2 * D + k];

    __shared__ float srow[4][D];
    for (int r0 = blockIdx.x * 4; r0 < rows; r0 += gridDim.x * 4) {
        int nr = min(4, rows - r0);
        for (int t = threadIdx.x; t < nr * D; t += blockDim.x)
            srow[t / D][t & (D - 1)] = src[(size_t)r0 * D + t];
        __syncthreads();
        float a0 = 0.f, a1 = 0.f, a2 = 0.f, a3 = 0.f;
        #pragma unroll
        for (int k = 0; k < D; k++) {
            float wv = wreg[k];
            a0 = fmaf(wv, srow[0][k], a0);
            a1 = fmaf(wv, srow[1][k], a1);
            a2 = fmaf(wv, srow[2][k], a2);
            a3 = fmaf(wv, srow[3][k], a3);
        }
        float acc[4] = {a0, a1, a2, a3};
        for (int j = 0; j < nr; j++)
            dst[(size_t)(r0 + j) * D + d] = acc[j];
        __syncthreads();
    }
}

__device__ __forceinline__ float lrelu(float x) { return x > 0.f ? x : 0.01f * x; }

__device__ __forceinline__ float warp_sum(float v) {
    #pragma unroll
    for (int off = 16; off; off >>= 1) v += __shfl_xor_sync(0xffffffffu, v, off);
    return v;
}

// ---------------- K1: edge pass 1 — relation routing + masked segment sums ----------------
__global__ __launch_bounds__(256) void edge_pass1(
    const int* __restrict__ uidx, const int* __restrict__ iidx,
    const float* __restrict__ user_emb, const float* __restrict__ entity_emb,
    const float* __restrict__ WW_b, const float* __restrict__ latent,
    const float* __restrict__ Pu, const float* __restrict__ Pi,
    float* __restrict__ s1, float* __restrict__ cnt,
    float* __restrict__ ysum, float* __restrict__ cnti,
    unsigned char* __restrict__ rtype, int E)
{
    int warp = (blockIdx.x * blockDim.x + threadIdx.x) >> 5;
    int lane = threadIdx.x & 31;
    int nwarps = (gridDim.x * blockDim.x) >> 5;
    int d0 = lane * 2;

    for (int e = warp; e < E; e += nwarps) {
        int u = uidx[e], it = iidx[e];
        float2 pu = *(const float2*)(Pu + (size_t)u * D + d0);
        float2 pi = *(const float2*)(Pi + (size_t)it * D + d0);
        float2 bb = *(const float2*)(WW_b + d0);
        float rx = lrelu(pu.x + pi.x + bb.x);
        float ry = lrelu(pu.y + pi.y + bb.y);

        float s0, s1s, s2;
        {
            float2 l0 = *(const float2*)(latent + 0 * D + d0);
            float2 l1 = *(const float2*)(latent + 1 * D + d0);
            float2 l2 = *(const float2*)(latent + 2 * D + d0);
            s0  = warp_sum(rx * l0.x + ry * l0.y);
            s1s = warp_sum(rx * l1.x + ry * l1.y);
            s2  = warp_sum(rx * l2.x + ry * l2.y);
        }
        int t = 0; float best = s0;
        if (s1s > best) { best = s1s; t = 1; }
        if (s2  > best) { best = s2;  t = 2; }

        // masked neighbor sum (u direction): s1[u, t, :] += entity_emb[it]
        float2 ie = *(const float2*)(entity_emb + (size_t)it * D + d0);
        float* s1p = s1 + ((size_t)u * NF + t) * D + d0;
        atomicAdd(s1p,     ie.x);
        atomicAdd(s1p + 1, ie.y);

        // entity direction: ysum[it, :] += user_emb[u]
        float2 ue = *(const float2*)(user_emb + (size_t)u * D + d0);
        float* ysp = ysum + (size_t)it * D + d0;
        atomicAdd(ysp,     ue.x);
        atomicAdd(ysp + 1, ue.y);

        if (lane == 0) {
            atomicAdd(cnt + (size_t)u * NF + t, 1.0f);
            atomicAdd(cnti + it, 1.0f);
            rtype[e] = (unsigned char)t;
        }
    }
}

// ---------------- K2: in-place segment mean ----------------
__global__ __launch_bounds__(256) void normalize_kernel(
    float* __restrict__ s1, const float* __restrict__ cnt,
    float* __restrict__ ysum, const float* __restrict__ cnti,
    long n1, long n2)
{
    long idx = blockIdx.x * (long)blockDim.x + threadIdx.x;
    long total = n1 + n2;
    long stride = (long)gridDim.x * blockDim.x;
    for (; idx < total; idx += stride) {
        if (idx < n1) {
            float c = cnt[idx >> 6];
            s1[idx] = s1[idx] / fmaxf(c, 1.0f);
        } else {
            long j = idx - n1;
            float c = cnti[j >> 6];
            ysum[j] = ysum[j] / fmaxf(c, 1.0f);
        }
    }
}

// ---------------- K3: edge pass 2 — similarity-weighted scatter ----------------
__global__ __launch_bounds__(256) void edge_pass2(
    const int* __restrict__ uidx, const int* __restrict__ iidx,
    const float* __restrict__ user_emb, const float* __restrict__ entity_emb,
    const float* __restrict__ WW_b, const float* __restrict__ WWi_b,
    const float* __restrict__ Pu, const float* __restrict__ Pi,
    const float* __restrict__ Qu, const float* __restrict__ Qi,
    const float* __restrict__ u_mean, const float* __restrict__ y_mean,
    const unsigned char* __restrict__ rtype,
    float* __restrict__ u2, float* __restrict__ y2, int E)
{
    int warp = (blockIdx.x * blockDim.x + threadIdx.x) >> 5;
    int lane = threadIdx.x & 31;
    int nwarps = (gridDim.x * blockDim.x) >> 5;
    int d0 = lane * 2;

    for (int e = warp; e < E; e += nwarps) {
        int u = uidx[e], it = iidx[e];
        int t = rtype[e];

        // recompute relation_ui
        float2 pu = *(const float2*)(Pu + (size_t)u * D + d0);
        float2 pi = *(const float2*)(Pi + (size_t)it * D + d0);
        float2 bb = *(const float2*)(WW_b + d0);
        float rx = lrelu(pu.x + pi.x + bb.x);
        float ry = lrelu(pu.y + pi.y + bb.y);

        float2 uv = *(const float2*)(u_mean + ((size_t)u * NF + t) * D + d0);
        float sim = warp_sum(rx * uv.x + ry * uv.y);

        float2 ie = *(const float2*)(entity_emb + (size_t)it * D + d0);
        float* u2p = u2 + ((size_t)u * NF + t) * D + d0;
        atomicAdd(u2p,     sim * ie.x);
        atomicAdd(u2p + 1, sim * ie.y);

        // relation_iu
        float2 qi = *(const float2*)(Qi + (size_t)it * D + d0);
        float2 qu = *(const float2*)(Qu + (size_t)u * D + d0);
        float2 bi = *(const float2*)(WWi_b + d0);
        float r2x = lrelu(qi.x + qu.x + bi.x);
        float r2y = lrelu(qi.y + qu.y + bi.y);

        float2 yv = *(const float2*)(y_mean + (size_t)it * D + d0);
        float sim_i = warp_sum(r2x * yv.x + r2y * yv.y);

        float2 ue = *(const float2*)(user_emb + (size_t)u * D + d0);
        float* y2p = y2 + (size_t)it * D + d0;
        atomicAdd(y2p,     sim_i * ue.x);
        atomicAdd(y2p + 1, sim_i * ue.y);
    }
}

// ---------------- K4: squash + residual + combine ----------------
__global__ __launch_bounds__(256) void finalize_entity(
    const float* __restrict__ y2, const float* __restrict__ cnti,
    const float* __restrict__ entity_emb, float* __restrict__ out, int ENT)
{
    int warp = (blockIdx.x * blockDim.x + threadIdx.x) >> 5;
    int lane = threadIdx.x & 31;
    int nwarps = (gridDim.x * blockDim.x) >> 5;
    int d0 = lane * 2;
    for (int row = warp; row < ENT; row += nwarps) {
        float c = fmaxf(cnti[row], 1.0f);
        float2 v = *(const float2*)(y2 + (size_t)row * D + d0);
        v.x /= c; v.y /= c;
        float n2 = warp_sum(v.x * v.x + v.y * v.y);
        float norm = sqrtf(n2);
        float scale = (n2 / (n2 + 1.0f)) / fmaxf(norm, 1e-12f);
        float2 ee = *(const float2*)(entity_emb + (size_t)row * D + d0);
        float2 o;
        o.x = scale * v.x + ee.x;
        o.y = scale * v.y + ee.y;
        *(float2*)(out + (size_t)row * D + d0) = o;
    }
}

__global__ __launch_bounds__(256) void finalize_user(
    const float* __restrict__ u2, const float* __restrict__ cnt,
    const float* __restrict__ user_emb, const float* __restrict__ w,
    float* __restrict__ out, int U)
{
    int warp = (blockIdx.x * blockDim.x + threadIdx.x) >> 5;
    int lane = threadIdx.x & 31;
    int nwarps = (gridDim.x * blockDim.x) >> 5;
    int d0 = lane * 2;

    float w0 = w[0], w1 = w[1], w2 = w[2];
    float m = fmaxf(w0, fmaxf(w1, w2));
    float e0 = expf(w0 - m), e1 = expf(w1 - m), e2 = expf(w2 - m);
    float inv = 1.0f / (e0 + e1 + e2);
    float ws[NF] = {e0 * inv, e1 * inv, e2 * inv};

    for (int row = warp; row < U; row += nwarps) {
        float2 ue = *(const float2*)(user_emb + (size_t)row * D + d0);
        float ax = 0.f, ay = 0.f;
        #pragma unroll
        for (int f = 0; f < NF; f++) {
            float c = fmaxf(cnt[(size_t)row * NF + f], 1.0f);
            float2 v = *(const float2*)(u2 + ((size_t)row * NF + f) * D + d0);
            v.x /= c; v.y /= c;
            float n2 = warp_sum(v.x * v.x + v.y * v.y);
            float norm = sqrtf(n2);
            float scale = (n2 / (n2 + 1.0f)) / fmaxf(norm, 1e-12f);
            ax += ws[f] * (scale * v.x + ue.x);
            ay += ws[f] * (scale * v.y + ue.y);
        }
        float2 o; o.x = ax; o.y = ay;
        *(float2*)(out + (size_t)row * D + d0) = o;
    }
}

// ---------------- host launcher ----------------
extern "C" void kernel_launch(void* const* d_in, const int* in_sizes, int n_in,
                              void* d_out, int out_size)
{
    const float* entity_emb = (const float*)d_in[0];
    const float* user_emb   = (const float*)d_in[1];
    const float* latent     = (const float*)d_in[2];
    const int*   uidx       = (const int*)d_in[3];
    const int*   iidx       = (const int*)d_in[4];
    const float* WW_w       = (const float*)d_in[5];
    const float* WW_b       = (const float*)d_in[6];
    const float* WWi_w      = (const float*)d_in[7];
    const float* WWi_b      = (const float*)d_in[8];
    const float* w          = (const float*)d_in[9];

    int ENT = in_sizes[0] / D;
    int U   = in_sizes[1] / D;
    int E   = in_sizes[3];

    float* out = (float*)d_out;

    float* tab; float* acc; unsigned char* rt;
    cudaGetSymbolAddress((void**)&tab, g_tab);
    cudaGetSymbolAddress((void**)&acc, g_acc);
    cudaGetSymbolAddress((void**)&rt,  g_rtype);

    float* Pu = tab;
    float* Pi = Pu + (size_t)U * D;
    float* Qu = Pi + (size_t)ENT * D;
    float* Qi = Qu + (size_t)U * D;

    float* s1   = acc;
    float* u2   = s1 + (size_t)U * NF * D;
    float* ys   = u2 + (size_t)U * NF * D;
    float* y2   = ys + (size_t)ENT * D;
    float* cnt  = y2 + (size_t)ENT * D;
    float* cnti = cnt + (size_t)U * NF;
    size_t accN = (size_t)U * NF * D * 2 + (size_t)ENT * D * 2 + (size_t)U * NF + ENT;

    cudaMemsetAsync(acc, 0, accN * sizeof(float));

    precompute_kernel<<<dim3(1024, 4), 64>>>(user_emb, entity_emb, WW_w, WWi_w,
                                             Pu, Pi, Qu, Qi, U, ENT);

    int eblocks = (E + 7) / 8;  // 8 warps per 256-thread block, one edge per warp
    edge_pass1<<<eblocks, 256>>>(uidx, iidx, user_emb, entity_emb, WW_b, latent,
                                 Pu, Pi, s1, cnt, ys, cnti, rt, E);

    long n1 = (long)U * NF * D, n2 = (long)ENT * D;
    normalize_kernel<<<4096, 256>>>(s1, cnt, ys, cnti, n1, n2);

    edge_pass2<<<eblocks, 256>>>(uidx, iidx, user_emb, entity_emb, WW_b, WWi_b,
                                 Pu, Pi, Qu, Qi, s1, ys, rt, u2, y2, E);

    finalize_entity<<<(ENT + 7) / 8, 256>>>(y2, cnti, entity_emb, out, ENT);
    finalize_user<<<(U + 7) / 8, 256>>>(u2, cnt, user_emb, w, out + (size_t)ENT * D, U);
}

// round 4
// speedup vs baseline: 1.1625x; 1.1625x over previous
#include <cuda_runtime.h>
#include <cuda_fp16.h>
#include <math.h>

#define D 64
#define NF 3
#define MAXU 100000
#define MAXENT 200000
#define MAXE 500000

typedef unsigned long long ull;

// ---------------- scratch (device globals) ----------------
// fp32 tables: Pu [U*D], Pi [ENT*D]  (routing-critical, stay fp32)
__device__ float g_tabf[(size_t)(MAXU + MAXENT) * D];
// fp16 tables: Qu [U*D], Qi [ENT*D], ue16 [U*D], ie16 [ENT*D]
__device__ __half g_tabh[(size_t)(MAXU + MAXENT) * 2 * D];
// per-edge relation_ui in fp16
__device__ __half g_rel[(size_t)MAXE * D];
// accumulators: s1 [U*3*D], u2 [U*3*D], ysum [ENT*D], y2 [ENT*D], cnt [U*3], cnti [ENT]
__device__ float g_acc[(size_t)MAXU * NF * D * 2 + (size_t)MAXENT * D * 2
                       + (size_t)MAXU * NF + MAXENT];
__device__ unsigned char g_rtype[MAXE];

// ---------------- helpers ----------------
__device__ __forceinline__ ull pk2(float a, float b) {
    ull r; asm("mov.b64 %0, {%1, %2};" : "=l"(r) : "f"(a), "f"(b)); return r;
}
__device__ __forceinline__ void fma2(ull& d, ull a, ull b) {
    asm("fma.rn.f32x2 %0, %1, %2, %0;" : "+l"(d) : "l"(a), "l"(b));
}
__device__ __forceinline__ float2 upk2(ull v) {
    float2 f; asm("mov.b64 {%0, %1}, %2;" : "=f"(f.x), "=f"(f.y) : "l"(v)); return f;
}
__device__ __forceinline__ float lrelu(float x) { return x > 0.f ? x : 0.01f * x; }

// sum over the 16 lanes of a half-warp
__device__ __forceinline__ float hsum16(float v) {
    v += __shfl_xor_sync(0xffffffffu, v, 8);
    v += __shfl_xor_sync(0xffffffffu, v, 4);
    v += __shfl_xor_sync(0xffffffffu, v, 2);
    v += __shfl_xor_sync(0xffffffffu, v, 1);
    return v;
}

// load 4 consecutive halfs -> float4 (8-byte aligned)
__device__ __forceinline__ float4 ldh4(const __half* p) {
    uint2 raw = *(const uint2*)p;
    __half2 a = *(__half2*)&raw.x;
    __half2 b = *(__half2*)&raw.y;
    float2 fa = __half22float2(a), fb = __half22float2(b);
    return make_float4(fa.x, fa.y, fb.x, fb.y);
}
__device__ __forceinline__ void sth4(__half* p, float4 v) {
    __half2 h0 = __floats2half2_rn(v.x, v.y);
    __half2 h1 = __floats2half2_rn(v.z, v.w);
    uint2 raw;
    raw.x = *(unsigned int*)&h0;
    raw.y = *(unsigned int*)&h1;
    *(uint2*)p = raw;
}
// vectorized global reduction (sm_90+)
__device__ __forceinline__ void red4(float* p, float4 v) {
    asm volatile("red.global.add.v4.f32 [%0], {%1, %2, %3, %4};"
                 :: "l"(p), "f"(v.x), "f"(v.y), "f"(v.z), "f"(v.w) : "memory");
}

// ---------------- K0: 4 node-level half-GEMMs (f32x2 packed) ----------------
// role 0: Pu (fp32) = user_emb   @ WW_w[:, :64].T
// role 1: Pi (fp32) = entity_emb @ WW_w[:, 64:].T
// role 2: Qu (fp16) = user_emb   @ WWi_w[:, 64:].T   (+ ue16 copy)
// role 3: Qi (fp16) = entity_emb @ WWi_w[:, :64].T   (+ ie16 copy)
__global__ __launch_bounds__(64) void precompute_kernel(
    const float* __restrict__ user_emb, const float* __restrict__ entity_emb,
    const float* __restrict__ WW_w, const float* __restrict__ WWi_w,
    float* __restrict__ Pu, float* __restrict__ Pi,
    __half* __restrict__ Qu, __half* __restrict__ Qi,
    __half* __restrict__ ue16, __half* __restrict__ ie16,
    int U, int ENT)
{
    int role = blockIdx.y;
    int d = threadIdx.x;  // 0..63  (output dim)
    const float* W; const float* src; float* dstf = 0; __half* dsth = 0;
    __half* cp = 0; int rows;
    if (role == 0)      { W = WW_w;           src = user_emb;   dstf = Pu; rows = U;   }
    else if (role == 1) { W = WW_w + D;       src = entity_emb; dstf = Pi; rows = ENT; }
    else if (role == 2) { W = WWi_w + D;      src = user_emb;   dsth = Qu; rows = U;   cp = ue16; }
    else                { W = WWi_w;          src = entity_emb; dsth = Qi; rows = ENT; cp = ie16; }

    float wreg[D];
    #pragma unroll
    for (int k = 0; k < D; k++) wreg[k] = W[(size_t)d * 2 * D + k];

    __shared__ float arr[D][4];  // arr[k][row]

    int lr = threadIdx.x & 3;    // loader row 0..3
    int lc = threadIdx.x >> 2;   // loader col-group 0..15

    for (int r0 = blockIdx.x * 4; r0 < rows; r0 += gridDim.x * 4) {
        // ---- load + transpose 4 rows into shared ----
        int row = r0 + lr;
        if (row < rows) {
            float4 v = *(const float4*)(src + (size_t)row * D + lc * 4);
            arr[lc * 4 + 0][lr] = v.x;
            arr[lc * 4 + 1][lr] = v.y;
            arr[lc * 4 + 2][lr] = v.z;
            arr[lc * 4 + 3][lr] = v.w;
            if (cp) sth4(cp + (size_t)row * D + lc * 4, v);
        }
        __syncthreads();

        ull a01 = pk2(0.f, 0.f), a23 = pk2(0.f, 0.f);
        #pragma unroll
        for (int k = 0; k < D; k++) {
            ull x01 = *(const ull*)&arr[k][0];
            ull x23 = *(const ull*)&arr[k][2];
            ull ww = pk2(wreg[k], wreg[k]);
            fma2(a01, ww, x01);
            fma2(a23, ww, x23);
        }
        float2 v01 = upk2(a01), v23 = upk2(a23);
        float res[4] = {v01.x, v01.y, v23.x, v23.y};

        if (dstf) {
            #pragma unroll
            for (int j = 0; j < 4; j++)
                if (r0 + j < rows) dstf[(size_t)(r0 + j) * D + d] = res[j];
        } else {
            #pragma unroll
            for (int j = 0; j < 4; j++)
                if (r0 + j < rows) dsth[(size_t)(r0 + j) * D + d] = __float2half(res[j]);
        }
        __syncthreads();
    }
}

// ---------------- K1: edge pass 1 — routing (fp32) + masked segment sums ----------------
// half-warp (16 lanes) per edge, 4 dims per lane
__global__ __launch_bounds__(256) void edge_pass1(
    const int* __restrict__ uidx, const int* __restrict__ iidx,
    const float* __restrict__ WW_b, const float* __restrict__ latent,
    const float* __restrict__ Pu, const float* __restrict__ Pi,
    const __half* __restrict__ ue16, const __half* __restrict__ ie16,
    float* __restrict__ s1, float* __restrict__ cnt,
    float* __restrict__ ysum, float* __restrict__ cnti,
    __half* __restrict__ rel_e, unsigned char* __restrict__ rtype, int E)
{
    int hw = (blockIdx.x * blockDim.x + threadIdx.x) >> 4;
    int l16 = threadIdx.x & 15;
    int nhw = (gridDim.x * blockDim.x) >> 4;
    int d0 = l16 * 4;

    float4 bb = *(const float4*)(WW_b + d0);
    float4 l0 = *(const float4*)(latent + 0 * D + d0);
    float4 l1 = *(const float4*)(latent + 1 * D + d0);
    float4 l2 = *(const float4*)(latent + 2 * D + d0);

    for (int e = hw; e < E; e += nhw) {
        int u = __ldg(uidx + e), it = __ldg(iidx + e);
        float4 pu = *(const float4*)(Pu + (size_t)u * D + d0);
        float4 pi = *(const float4*)(Pi + (size_t)it * D + d0);
        float4 r;
        r.x = lrelu(pu.x + pi.x + bb.x);
        r.y = lrelu(pu.y + pi.y + bb.y);
        r.z = lrelu(pu.z + pi.z + bb.z);
        r.w = lrelu(pu.w + pi.w + bb.w);

        float s0 = hsum16(r.x * l0.x + r.y * l0.y + r.z * l0.z + r.w * l0.w);
        float s1v = hsum16(r.x * l1.x + r.y * l1.y + r.z * l1.z + r.w * l1.w);
        float s2 = hsum16(r.x * l2.x + r.y * l2.y + r.z * l2.z + r.w * l2.w);

        int t = 0; float best = s0;
        if (s1v > best) { best = s1v; t = 1; }
        if (s2  > best) { best = s2;  t = 2; }

        // store relation vector fp16 for pass 2
        sth4(rel_e + (size_t)e * D + d0, r);

        // masked neighbor sum: s1[u, t, :] += entity_emb[it]
        float4 ie = ldh4(ie16 + (size_t)it * D + d0);
        red4(s1 + ((size_t)u * NF + t) * D + d0, ie);

        // entity direction: ysum[it, :] += user_emb[u]
        float4 ue = ldh4(ue16 + (size_t)u * D + d0);
        red4(ysum + (size_t)it * D + d0, ue);

        if (l16 == 0) {
            atomicAdd(cnt + (size_t)u * NF + t, 1.0f);
            atomicAdd(cnti + it, 1.0f);
            rtype[e] = (unsigned char)t;
        }
    }
}

// ---------------- K3: edge pass 2 — similarity-weighted scatter ----------------
__global__ __launch_bounds__(256) void edge_pass2(
    const int* __restrict__ uidx, const int* __restrict__ iidx,
    const float* __restrict__ WWi_b,
    const __half* __restrict__ Qu, const __half* __restrict__ Qi,
    const __half* __restrict__ ue16, const __half* __restrict__ ie16,
    const __half* __restrict__ rel_e, const unsigned char* __restrict__ rtype,
    const float* __restrict__ s1raw, const float* __restrict__ cnt,
    const float* __restrict__ ysraw, const float* __restrict__ cnti,
    float* __restrict__ u2, float* __restrict__ y2, int E)
{
    int hw = (blockIdx.x * blockDim.x + threadIdx.x) >> 4;
    int l16 = threadIdx.x & 15;
    int nhw = (gridDim.x * blockDim.x) >> 4;
    int d0 = l16 * 4;

    float4 bi = *(const float4*)(WWi_b + d0);

    for (int e = hw; e < E; e += nhw) {
        int u = __ldg(uidx + e), it = __ldg(iidx + e);
        int t = rtype[e];

        // sim = dot(rel_ui, s1[u,t]/cnt)
        float4 r = ldh4(rel_e + (size_t)e * D + d0);
        float4 um = *(const float4*)(s1raw + ((size_t)u * NF + t) * D + d0);
        float c = __ldg(cnt + (size_t)u * NF + t);
        float sim = hsum16(r.x * um.x + r.y * um.y + r.z * um.z + r.w * um.w)
                  / fmaxf(c, 1.0f);

        float4 ie = ldh4(ie16 + (size_t)it * D + d0);
        red4(u2 + ((size_t)u * NF + t) * D + d0,
             make_float4(sim * ie.x, sim * ie.y, sim * ie.z, sim * ie.w));

        // relation_iu (fp16 tables, smooth path)
        float4 qi = ldh4(Qi + (size_t)it * D + d0);
        float4 qu = ldh4(Qu + (size_t)u * D + d0);
        float4 r2;
        r2.x = lrelu(qi.x + qu.x + bi.x);
        r2.y = lrelu(qi.y + qu.y + bi.y);
        r2.z = lrelu(qi.z + qu.z + bi.z);
        r2.w = lrelu(qi.w + qu.w + bi.w);

        float4 ym = *(const float4*)(ysraw + (size_t)it * D + d0);
        float ci = __ldg(cnti + it);
        float sim_i = hsum16(r2.x * ym.x + r2.y * ym.y + r2.z * ym.z + r2.w * ym.w)
                    / fmaxf(ci, 1.0f);

        float4 ue = ldh4(ue16 + (size_t)u * D + d0);
        red4(y2 + (size_t)it * D + d0,
             make_float4(sim_i * ue.x, sim_i * ue.y, sim_i * ue.z, sim_i * ue.w));
    }
}

__device__ __forceinline__ float warp_sum(float v) {
    #pragma unroll
    for (int off = 16; off; off >>= 1) v += __shfl_xor_sync(0xffffffffu, v, off);
    return v;
}

// ---------------- K4: squash + residual + combine ----------------
__global__ __launch_bounds__(256) void finalize_entity(
    const float* __restrict__ y2, const float* __restrict__ cnti,
    const float* __restrict__ entity_emb, float* __restrict__ out, int ENT)
{
    int warp = (blockIdx.x * blockDim.x + threadIdx.x) >> 5;
    int lane = threadIdx.x & 31;
    int nwarps = (gridDim.x * blockDim.x) >> 5;
    int d0 = lane * 2;
    for (int row = warp; row < ENT; row += nwarps) {
        float c = fmaxf(cnti[row], 1.0f);
        float2 v = *(const float2*)(y2 + (size_t)row * D + d0);
        v.x /= c; v.y /= c;
        float n2 = warp_sum(v.x * v.x + v.y * v.y);
        float norm = sqrtf(n2);
        float scale = (n2 / (n2 + 1.0f)) / fmaxf(norm, 1e-12f);
        float2 ee = *(const float2*)(entity_emb + (size_t)row * D + d0);
        float2 o;
        o.x = scale * v.x + ee.x;
        o.y = scale * v.y + ee.y;
        *(float2*)(out + (size_t)row * D + d0) = o;
    }
}

__global__ __launch_bounds__(256) void finalize_user(
    const float* __restrict__ u2, const float* __restrict__ cnt,
    const float* __restrict__ user_emb, const float* __restrict__ w,
    float* __restrict__ out, int U)
{
    int warp = (blockIdx.x * blockDim.x + threadIdx.x) >> 5;
    int lane = threadIdx.x & 31;
    int nwarps = (gridDim.x * blockDim.x) >> 5;
    int d0 = lane * 2;

    float w0 = w[0], w1 = w[1], w2 = w[2];
    float m = fmaxf(w0, fmaxf(w1, w2));
    float e0 = expf(w0 - m), e1 = expf(w1 - m), e2 = expf(w2 - m);
    float inv = 1.0f / (e0 + e1 + e2);
    float ws[NF] = {e0 * inv, e1 * inv, e2 * inv};

    for (int row = warp; row < U; row += nwarps) {
        float2 ue = *(const float2*)(user_emb + (size_t)row * D + d0);
        float ax = 0.f, ay = 0.f;
        #pragma unroll
        for (int f = 0; f < NF; f++) {
            float c = fmaxf(cnt[(size_t)row * NF + f], 1.0f);
            float2 v = *(const float2*)(u2 + ((size_t)row * NF + f) * D + d0);
            v.x /= c; v.y /= c;
            float n2 = warp_sum(v.x * v.x + v.y * v.y);
            float norm = sqrtf(n2);
            float scale = (n2 / (n2 + 1.0f)) / fmaxf(norm, 1e-12f);
            ax += ws[f] * (scale * v.x + ue.x);
            ay += ws[f] * (scale * v.y + ue.y);
        }
        float2 o; o.x = ax; o.y = ay;
        *(float2*)(out + (size_t)row * D + d0) = o;
    }
}

// ---------------- host launcher ----------------
extern "C" void kernel_launch(void* const* d_in, const int* in_sizes, int n_in,
                              void* d_out, int out_size)
{
    const float* entity_emb = (const float*)d_in[0];
    const float* user_emb   = (const float*)d_in[1];
    const float* latent     = (const float*)d_in[2];
    const int*   uidx       = (const int*)d_in[3];
    const int*   iidx       = (const int*)d_in[4];
    const float* WW_w       = (const float*)d_in[5];
    const float* WW_b       = (const float*)d_in[6];
    const float* WWi_w      = (const float*)d_in[7];
    const float* WWi_b      = (const float*)d_in[8];
    const float* w          = (const float*)d_in[9];

    int ENT = in_sizes[0] / D;
    int U   = in_sizes[1] / D;
    int E   = in_sizes[3];

    float* out = (float*)d_out;

    float* tabf; __half* tabh; __half* rel; float* acc; unsigned char* rt;
    cudaGetSymbolAddress((void**)&tabf, g_tabf);
    cudaGetSymbolAddress((void**)&tabh, g_tabh);
    cudaGetSymbolAddress((void**)&rel,  g_rel);
    cudaGetSymbolAddress((void**)&acc,  g_acc);
    cudaGetSymbolAddress((void**)&rt,   g_rtype);

    float* Pu = tabf;
    float* Pi = Pu + (size_t)U * D;
    __half* Qu   = tabh;
    __half* Qi   = Qu + (size_t)U * D;
    __half* ue16 = Qi + (size_t)ENT * D;
    __half* ie16 = ue16 + (size_t)U * D;

    float* s1   = acc;
    float* u2   = s1 + (size_t)U * NF * D;
    float* ys   = u2 + (size_t)U * NF * D;
    float* y2   = ys + (size_t)ENT * D;
    float* cnt  = y2 + (size_t)ENT * D;
    float* cnti = cnt + (size_t)U * NF;
    size_t accN = (size_t)U * NF * D * 2 + (size_t)ENT * D * 2 + (size_t)U * NF + ENT;

    cudaMemsetAsync(acc, 0, accN * sizeof(float));

    precompute_kernel<<<dim3(4096, 4), 64>>>(user_emb, entity_emb, WW_w, WWi_w,
                                             Pu, Pi, Qu, Qi, ue16, ie16, U, ENT);

    int eblocks = (E + 15) / 16;  // 16 edges per 256-thread block (half-warp per edge)
    edge_pass1<<<eblocks, 256>>>(uidx, iidx, WW_b, latent, Pu, Pi, ue16, ie16,
                                 s1, cnt, ys, cnti, rel, rt, E);

    edge_pass2<<<eblocks, 256>>>(uidx, iidx, WWi_b, Qu, Qi, ue16, ie16, rel, rt,
                                 s1, cnt, ys, cnti, u2, y2, E);

    finalize_entity<<<(ENT + 7) / 8, 256>>>(y2, cnti, entity_emb, out, ENT);
    finalize_user<<<(U + 7) / 8, 256>>>(u2, cnt, user_emb, w, out + (size_t)ENT * D, U);
}

// round 9
// speedup vs baseline: 1.3395x; 1.1523x over previous
#include <cuda_runtime.h>
#include <cuda_fp16.h>
#include <math.h>

#define D 64
#define NF 3
#define MAXU 100000
#define MAXENT 200000
#define MAXE 500000

typedef unsigned long long ull;

// ---------------- scratch (device globals) ----------------
// fp32 tables (routing-critical): Pu [U*D], Pi [ENT*D]
__device__ __align__(256) float g_tabf[(size_t)(MAXU + MAXENT) * D];
// fp16 tables: Qu [U*D], Qi [ENT*D], ue16 [U*D], ie16 [ENT*D]
__device__ __align__(256) __half g_tabh[(size_t)(MAXU + MAXENT) * 2 * D];
// per-edge relation_ui in fp16
__device__ __align__(256) __half g_rel[(size_t)MAXE * D];
// accumulators: s1 [U*3*D], u2 [U*3*D], ysum [ENT*D], y2 [ENT*D], cnt [U*3], cnti [ENT]
__device__ __align__(256) float g_acc[(size_t)MAXU * NF * D * 2 + (size_t)MAXENT * D * 2
                                      + (size_t)MAXU * NF + MAXENT];
__device__ __align__(256) unsigned char g_rtype[MAXE];

// ---------------- helpers ----------------
__device__ __forceinline__ ull pk2(float a, float b) {
    ull r; asm("mov.b64 %0, {%1, %2};" : "=l"(r) : "f"(a), "f"(b)); return r;
}
__device__ __forceinline__ void fma2(ull& d, ull a, ull b) {
    asm("fma.rn.f32x2 %0, %1, %2, %0;" : "+l"(d) : "l"(a), "l"(b));
}
__device__ __forceinline__ float2 upk2(ull v) {
    float2 f; asm("mov.b64 {%0, %1}, %2;" : "=f"(f.x), "=f"(f.y) : "l"(v)); return f;
}
__device__ __forceinline__ float lrelu(float x) { return x > 0.f ? x : 0.01f * x; }

// sum over 16 lanes of a half-warp (halves independent)
__device__ __forceinline__ float hsum16(float v) {
    v += __shfl_xor_sync(0xffffffffu, v, 8);
    v += __shfl_xor_sync(0xffffffffu, v, 4);
    v += __shfl_xor_sync(0xffffffffu, v, 2);
    v += __shfl_xor_sync(0xffffffffu, v, 1);
    return v;
}

__device__ __forceinline__ float4 ldh4(const __half* p) {
    uint2 raw = *(const uint2*)p;
    __half2 a = *(__half2*)&raw.x;
    __half2 b = *(__half2*)&raw.y;
    float2 fa = __half22float2(a), fb = __half22float2(b);
    return make_float4(fa.x, fa.y, fb.x, fb.y);
}
__device__ __forceinline__ void sth4(__half* p, float4 v) {
    __half2 h0 = __floats2half2_rn(v.x, v.y);
    __half2 h1 = __floats2half2_rn(v.z, v.w);
    uint2 raw;
    raw.x = *(unsigned int*)&h0;
    raw.y = *(unsigned int*)&h1;
    *(uint2*)p = raw;
}
__device__ __forceinline__ void red4(float* p, float4 v) {
    asm volatile("red.global.add.v4.f32 [%0], {%1, %2, %3, %4};"
                 :: "l"(p), "f"(v.x), "f"(v.y), "f"(v.z), "f"(v.w) : "memory");
}

// ---------------- K0: 4 node-level half-GEMMs ----------------
// role 0: Pu (fp32) = user_emb   @ WW_w[:, :64].T
// role 1: Pi (fp32) = entity_emb @ WW_w[:, 64:].T
// role 2: Qu (fp16) = user_emb   @ WWi_w[:, 64:].T   (+ ue16 copy)
// role 3: Qi (fp16) = entity_emb @ WWi_w[:, :64].T   (+ ie16 copy)
__global__ __launch_bounds__(64) void precompute_kernel(
    const float* __restrict__ user_emb, const float* __restrict__ entity_emb,
    const float* __restrict__ WW_w, const float* __restrict__ WWi_w,
    float* __restrict__ Pu, float* __restrict__ Pi,
    __half* __restrict__ Qu, __half* __restrict__ Qi,
    __half* __restrict__ ue16, __half* __restrict__ ie16,
    int U, int ENT)
{
    int role = blockIdx.y;
    int d = threadIdx.x;
    const float* W; const float* src; float* dstf = 0; __half* dsth = 0;
    __half* cp = 0; int rows;
    if (role == 0)      { W = WW_w;           src = user_emb;   dstf = Pu; rows = U;   }
    else if (role == 1) { W = WW_w + D;       src = entity_emb; dstf = Pi; rows = ENT; }
    else if (role == 2) { W = WWi_w + D;      src = user_emb;   dsth = Qu; rows = U;   cp = ue16; }
    else                { W = WWi_w;          src = entity_emb; dsth = Qi; rows = ENT; cp = ie16; }

    float wreg[D];
    #pragma unroll
    for (int k = 0; k < D; k++) wreg[k] = W[(size_t)d * 2 * D + k];

    __shared__ float arr[D][4];

    int lr = threadIdx.x & 3;
    int lc = threadIdx.x >> 2;

    for (int r0 = blockIdx.x * 4; r0 < rows; r0 += gridDim.x * 4) {
        int row = r0 + lr;
        if (row < rows) {
            float4 v = *(const float4*)(src + (size_t)row * D + lc * 4);
            arr[lc * 4 + 0][lr] = v.x;
            arr[lc * 4 + 1][lr] = v.y;
            arr[lc * 4 + 2][lr] = v.z;
            arr[lc * 4 + 3][lr] = v.w;
            if (cp) sth4(cp + (size_t)row * D + lc * 4, v);
        }
        __syncthreads();

        ull a01 = pk2(0.f, 0.f), a23 = pk2(0.f, 0.f);
        #pragma unroll
        for (int k = 0; k < D; k++) {
            ull x01 = *(const ull*)&arr[k][0];
            ull x23 = *(const ull*)&arr[k][2];
            ull ww = pk2(wreg[k], wreg[k]);
            fma2(a01, ww, x01);
            fma2(a23, ww, x23);
        }
        float2 v01 = upk2(a01), v23 = upk2(a23);
        float res[4] = {v01.x, v01.y, v23.x, v23.y};

        if (dstf) {
            #pragma unroll
            for (int j = 0; j < 4; j++)
                if (r0 + j < rows) dstf[(size_t)(r0 + j) * D + d] = res[j];
        } else {
            #pragma unroll
            for (int j = 0; j < 4; j++)
                if (r0 + j < rows) dsth[(size_t)(r0 + j) * D + d] = __float2half(res[j]);
        }
        __syncthreads();
    }
}

// ---------------- K1: edge pass 1 — 2 edges per half-warp (MLP) ----------------
__global__ __launch_bounds__(256) void edge_pass1(
    const int* __restrict__ uidx, const int* __restrict__ iidx,
    const float* __restrict__ WW_b, const float* __restrict__ latent,
    const float* __restrict__ Pu, const float* __restrict__ Pi,
    const __half* __restrict__ ue16, const __half* __restrict__ ie16,
    float* __restrict__ s1, float* __restrict__ cnt,
    float* __restrict__ ysum, float* __restrict__ cnti,
    __half* __restrict__ rel_e, unsigned char* __restrict__ rtype, int E)
{
    int p = (blockIdx.x * blockDim.x + threadIdx.x) >> 4;
    int l16 = threadIdx.x & 15;
    int np = (gridDim.x * blockDim.x) >> 4;
    int d0 = l16 * 4;

    float4 bb = *(const float4*)(WW_b + d0);
    float4 l0 = *(const float4*)(latent + 0 * D + d0);
    float4 l1 = *(const float4*)(latent + 1 * D + d0);
    float4 l2 = *(const float4*)(latent + 2 * D + d0);

    for (int e0 = p * 2; e0 < E; e0 += np * 2) {
        int e1 = e0 + 1;
        bool has1 = (e1 < E);
        int u0 = __ldg(uidx + e0), i0 = __ldg(iidx + e0);
        int u1 = has1 ? __ldg(uidx + e1) : u0;
        int i1 = has1 ? __ldg(iidx + e1) : i0;

        // ---- issue all gathers up front (MLP) ----
        float4 pu0 = *(const float4*)(Pu + (size_t)u0 * D + d0);
        float4 pi0 = *(const float4*)(Pi + (size_t)i0 * D + d0);
        float4 pu1 = *(const float4*)(Pu + (size_t)u1 * D + d0);
        float4 pi1 = *(const float4*)(Pi + (size_t)i1 * D + d0);
        float4 ie0 = ldh4(ie16 + (size_t)i0 * D + d0);
        float4 ue0 = ldh4(ue16 + (size_t)u0 * D + d0);
        float4 ie1 = ldh4(ie16 + (size_t)i1 * D + d0);
        float4 ue1 = ldh4(ue16 + (size_t)u1 * D + d0);

        // ---- edge 0 routing ----
        float4 r0;
        r0.x = lrelu(pu0.x + pi0.x + bb.x);
        r0.y = lrelu(pu0.y + pi0.y + bb.y);
        r0.z = lrelu(pu0.z + pi0.z + bb.z);
        r0.w = lrelu(pu0.w + pi0.w + bb.w);
        float a0 = hsum16(r0.x * l0.x + r0.y * l0.y + r0.z * l0.z + r0.w * l0.w);
        float a1 = hsum16(r0.x * l1.x + r0.y * l1.y + r0.z * l1.z + r0.w * l1.w);
        float a2 = hsum16(r0.x * l2.x + r0.y * l2.y + r0.z * l2.z + r0.w * l2.w);
        int t0 = 0; float best0 = a0;
        if (a1 > best0) { best0 = a1; t0 = 1; }
        if (a2 > best0) { best0 = a2; t0 = 2; }

        // ---- edge 1 routing ----
        float4 r1;
        r1.x = lrelu(pu1.x + pi1.x + bb.x);
        r1.y = lrelu(pu1.y + pi1.y + bb.y);
        r1.z = lrelu(pu1.z + pi1.z + bb.z);
        r1.w = lrelu(pu1.w + pi1.w + bb.w);
        float b0 = hsum16(r1.x * l0.x + r1.y * l0.y + r1.z * l0.z + r1.w * l0.w);
        float b1 = hsum16(r1.x * l1.x + r1.y * l1.y + r1.z * l1.z + r1.w * l1.w);
        float b2 = hsum16(r1.x * l2.x + r1.y * l2.y + r1.z * l2.z + r1.w * l2.w);
        int t1 = 0; float best1 = b0;
        if (b1 > best1) { best1 = b1; t1 = 1; }
        if (b2 > best1) { best1 = b2; t1 = 2; }

        // ---- stores/scatters ----
        sth4(rel_e + (size_t)e0 * D + d0, r0);
        red4(s1 + ((size_t)u0 * NF + t0) * D + d0, ie0);
        red4(ysum + (size_t)i0 * D + d0, ue0);
        if (has1) {
            sth4(rel_e + (size_t)e1 * D + d0, r1);
            red4(s1 + ((size_t)u1 * NF + t1) * D + d0, ie1);
            red4(ysum + (size_t)i1 * D + d0, ue1);
        }
        if (l16 == 0) {
            atomicAdd(cnt + (size_t)u0 * NF + t0, 1.0f);
            atomicAdd(cnti + i0, 1.0f);
            rtype[e0] = (unsigned char)t0;
            if (has1) {
                atomicAdd(cnt + (size_t)u1 * NF + t1, 1.0f);
                atomicAdd(cnti + i1, 1.0f);
                rtype[e1] = (unsigned char)t1;
            }
        }
    }
}

// ---------------- K3: edge pass 2 — 2 edges per half-warp ----------------
__global__ __launch_bounds__(256) void edge_pass2(
    const int* __restrict__ uidx, const int* __restrict__ iidx,
    const float* __restrict__ WWi_b,
    const __half* __restrict__ Qu, const __half* __restrict__ Qi,
    const __half* __restrict__ ue16, const __half* __restrict__ ie16,
    const __half* __restrict__ rel_e, const unsigned char* __restrict__ rtype,
    const float* __restrict__ s1raw, const float* __restrict__ cnt,
    const float* __restrict__ ysraw, const float* __restrict__ cnti,
    float* __restrict__ u2, float* __restrict__ y2, int E)
{
    int p = (blockIdx.x * blockDim.x + threadIdx.x) >> 4;
    int l16 = threadIdx.x & 15;
    int np = (gridDim.x * blockDim.x) >> 4;
    int d0 = l16 * 4;

    float4 bi = *(const float4*)(WWi_b + d0);

    for (int e0 = p * 2; e0 < E; e0 += np * 2) {
        int e1 = e0 + 1;
        bool has1 = (e1 < E);
        int u0 = __ldg(uidx + e0), i0 = __ldg(iidx + e0);
        int u1 = has1 ? __ldg(uidx + e1) : u0;
        int i1 = has1 ? __ldg(iidx + e1) : i0;
        int t0 = rtype[e0];
        int t1 = has1 ? rtype[e1] : t0;

        // ---- issue all gathers up front ----
        float4 r0  = ldh4(rel_e + (size_t)e0 * D + d0);
        float4 um0 = *(const float4*)(s1raw + ((size_t)u0 * NF + t0) * D + d0);
        float4 ie0 = ldh4(ie16 + (size_t)i0 * D + d0);
        float4 qi0 = ldh4(Qi + (size_t)i0 * D + d0);
        float4 qu0 = ldh4(Qu + (size_t)u0 * D + d0);
        float4 ym0 = *(const float4*)(ysraw + (size_t)i0 * D + d0);
        float4 ue0 = ldh4(ue16 + (size_t)u0 * D + d0);
        float  c0  = __ldg(cnt + (size_t)u0 * NF + t0);
        float  ci0 = __ldg(cnti + i0);

        float4 r1  = ldh4(rel_e + (size_t)e1 * D * (has1 ? 1 : 0) + d0);
        float4 um1 = *(const float4*)(s1raw + ((size_t)u1 * NF + t1) * D + d0);
        float4 ie1 = ldh4(ie16 + (size_t)i1 * D + d0);
        float4 qi1 = ldh4(Qi + (size_t)i1 * D + d0);
        float4 qu1 = ldh4(Qu + (size_t)u1 * D + d0);
        float4 ym1 = *(const float4*)(ysraw + (size_t)i1 * D + d0);
        float4 ue1 = ldh4(ue16 + (size_t)u1 * D + d0);
        float  c1  = has1 ? __ldg(cnt + (size_t)u1 * NF + t1) : 1.f;
        float  ci1 = has1 ? __ldg(cnti + i1) : 1.f;

        // ---- edge 0 ----
        float sim0 = hsum16(r0.x * um0.x + r0.y * um0.y + r0.z * um0.z + r0.w * um0.w)
                   / fmaxf(c0, 1.0f);
        red4(u2 + ((size_t)u0 * NF + t0) * D + d0,
             make_float4(sim0 * ie0.x, sim0 * ie0.y, sim0 * ie0.z, sim0 * ie0.w));

        float4 rr0;
        rr0.x = lrelu(qi0.x + qu0.x + bi.x);
        rr0.y = lrelu(qi0.y + qu0.y + bi.y);
        rr0.z = lrelu(qi0.z + qu0.z + bi.z);
        rr0.w = lrelu(qi0.w + qu0.w + bi.w);
        float simi0 = hsum16(rr0.x * ym0.x + rr0.y * ym0.y + rr0.z * ym0.z + rr0.w * ym0.w)
                    / fmaxf(ci0, 1.0f);
        red4(y2 + (size_t)i0 * D + d0,
             make_float4(simi0 * ue0.x, simi0 * ue0.y, simi0 * ue0.z, simi0 * ue0.w));

        // ---- edge 1 ----
        if (has1) {
            float sim1 = hsum16(r1.x * um1.x + r1.y * um1.y + r1.z * um1.z + r1.w * um1.w)
                       / fmaxf(c1, 1.0f);
            red4(u2 + ((size_t)u1 * NF + t1) * D + d0,
                 make_float4(sim1 * ie1.x, sim1 * ie1.y, sim1 * ie1.z, sim1 * ie1.w));

            float4 rr1;
            rr1.x = lrelu(qi1.x + qu1.x + bi.x);
            rr1.y = lrelu(qi1.y + qu1.y + bi.y);
            rr1.z = lrelu(qi1.z + qu1.z + bi.z);
            rr1.w = lrelu(qi1.w + qu1.w + bi.w);
            float simi1 = hsum16(rr1.x * ym1.x + rr1.y * ym1.y + rr1.z * ym1.z + rr1.w * ym1.w)
                        / fmaxf(ci1, 1.0f);
            red4(y2 + (size_t)i1 * D + d0,
                 make_float4(simi1 * ue1.x, simi1 * ue1.y, simi1 * ue1.z, simi1 * ue1.w));
        }
    }
}

// ---------------- K4: squash + residual + combine ----------------
__global__ __launch_bounds__(256) void finalize_entity(
    const float* __restrict__ y2, const float* __restrict__ cnti,
    const float* __restrict__ entity_emb, float* __restrict__ out, int ENT)
{
    int g = blockIdx.x * blockDim.x + threadIdx.x;
    int row = g >> 4;
    int l16 = threadIdx.x & 15;
    int nrows = (gridDim.x * blockDim.x) >> 4;
    int d0 = l16 * 4;
    for (; row < ENT; row += nrows) {
        float inv = 1.0f / fmaxf(cnti[row], 1.0f);
        float4 v = *(const float4*)(y2 + (size_t)row * D + d0);
        v.x *= inv; v.y *= inv; v.z *= inv; v.w *= inv;
        float n2 = hsum16(v.x * v.x + v.y * v.y + v.z * v.z + v.w * v.w);
        float norm = sqrtf(n2);
        float scale = (n2 / (n2 + 1.0f)) / fmaxf(norm, 1e-12f);
        float4 ee = *(const float4*)(entity_emb + (size_t)row * D + d0);
        float4 o;
        o.x = fmaf(scale, v.x, ee.x);
        o.y = fmaf(scale, v.y, ee.y);
        o.z = fmaf(scale, v.z, ee.z);
        o.w = fmaf(scale, v.w, ee.w);
        *(float4*)(out + (size_t)row * D + d0) = o;
    }
}

__global__ __launch_bounds__(256) void finalize_user(
    const float* __restrict__ u2, const float* __restrict__ cnt,
    const float* __restrict__ user_emb, const float* __restrict__ w,
    float* __restrict__ out, int U)
{
    int g = blockIdx.x * blockDim.x + threadIdx.x;
    int row = g >> 4;
    int l16 = threadIdx.x & 15;
    int nrows = (gridDim.x * blockDim.x) >> 4;
    int d0 = l16 * 4;

    float w0 = w[0], w1 = w[1], w2 = w[2];
    float m = fmaxf(w0, fmaxf(w1, w2));
    float e0 = expf(w0 - m), e1 = expf(w1 - m), e2 = expf(w2 - m);
    float inv3 = 1.0f / (e0 + e1 + e2);
    float ws[NF] = {e0 * inv3, e1 * inv3, e2 * inv3};

    for (; row < U; row += nrows) {
        float4 ue = *(const float4*)(user_emb + (size_t)row * D + d0);
        float4 a = make_float4(0.f, 0.f, 0.f, 0.f);
        #pragma unroll
        for (int f = 0; f < NF; f++) {
            float inv = 1.0f / fmaxf(cnt[(size_t)row * NF + f], 1.0f);
            float4 v = *(const float4*)(u2 + ((size_t)row * NF + f) * D + d0);
            v.x *= inv; v.y *= inv; v.z *= inv; v.w *= inv;
            float n2 = hsum16(v.x * v.x + v.y * v.y + v.z * v.z + v.w * v.w);
            float norm = sqrtf(n2);
            float scale = (n2 / (n2 + 1.0f)) / fmaxf(norm, 1e-12f);
            a.x += ws[f] * fmaf(scale, v.x, ue.x);
            a.y += ws[f] * fmaf(scale, v.y, ue.y);
            a.z += ws[f] * fmaf(scale, v.z, ue.z);
            a.w += ws[f] * fmaf(scale, v.w, ue.w);
        }
        *(float4*)(out + (size_t)row * D + d0) = a;
    }
}

// ---------------- host launcher ----------------
extern "C" void kernel_launch(void* const* d_in, const int* in_sizes, int n_in,
                              void* d_out, int out_size)
{
    const float* entity_emb = (const float*)d_in[0];
    const float* user_emb   = (const float*)d_in[1];
    const float* latent     = (const float*)d_in[2];
    const int*   uidx       = (const int*)d_in[3];
    const int*   iidx       = (const int*)d_in[4];
    const float* WW_w       = (const float*)d_in[5];
    const float* WW_b       = (const float*)d_in[6];
    const float* WWi_w      = (const float*)d_in[7];
    const float* WWi_b      = (const float*)d_in[8];
    const float* w          = (const float*)d_in[9];

    int ENT = in_sizes[0] / D;
    int U   = in_sizes[1] / D;
    int E   = in_sizes[3];

    float* out = (float*)d_out;

    float* tabf; __half* tabh; __half* rel; float* acc; unsigned char* rt;
    cudaGetSymbolAddress((void**)&tabf, g_tabf);
    cudaGetSymbolAddress((void**)&tabh, g_tabh);
    cudaGetSymbolAddress((void**)&rel,  g_rel);
    cudaGetSymbolAddress((void**)&acc,  g_acc);
    cudaGetSymbolAddress((void**)&rt,   g_rtype);

    float* Pu = tabf;
    float* Pi = Pu + (size_t)U * D;
    __half* Qu   = tabh;
    __half* Qi   = Qu + (size_t)U * D;
    __half* ue16 = Qi + (size_t)ENT * D;
    __half* ie16 = ue16 + (size_t)U * D;

    float* s1   = acc;
    float* u2   = s1 + (size_t)U * NF * D;
    float* ys   = u2 + (size_t)U * NF * D;
    float* y2   = ys + (size_t)ENT * D;
    float* cnt  = y2 + (size_t)ENT * D;
    float* cnti = cnt + (size_t)U * NF;
    size_t accN = (size_t)U * NF * D * 2 + (size_t)ENT * D * 2 + (size_t)U * NF + ENT;

    cudaMemsetAsync(acc, 0, accN * sizeof(float));

    precompute_kernel<<<dim3(4096, 4), 64>>>(user_emb, entity_emb, WW_w, WWi_w,
                                             Pu, Pi, Qu, Qi, ue16, ie16, U, ENT);

    int eblocks = (E + 31) / 32;  // 16 half-warps/block × 2 edges each
    edge_pass1<<<eblocks, 256>>>(uidx, iidx, WW_b, latent, Pu, Pi, ue16, ie16,
                                 s1, cnt, ys, cnti, rel, rt, E);

    edge_pass2<<<eblocks, 256>>>(uidx, iidx, WWi_b, Qu, Qi, ue16, ie16, rel, rt,
                                 s1, cnt, ys, cnti, u2, y2, E);

    finalize_entity<<<(ENT * 16 + 255) / 256, 256>>>(y2, cnti, entity_emb, out, ENT);
    finalize_user<<<(U * 16 + 255) / 256, 256>>>(u2, cnt, user_emb, w, out + (size_t)ENT * D, U);
}

// round 11
// speedup vs baseline: 1.4573x; 1.0879x over previous
#include <cuda_runtime.h>
#include <cuda_fp16.h>
#include <math.h>

#define D 64
#define NF 3
#define MAXU 100000
#define MAXENT 200000
#define MAXE 500000

typedef unsigned long long ull;

// ---------------- scratch (device globals) ----------------
// fp32 tables (routing-critical): Pu [U*D], Pi [ENT*D]
__device__ __align__(256) float g_tabf[(size_t)(MAXU + MAXENT) * D];
// fp16 tables: Qu [U*D], Qi [ENT*D], ue16 [U*D], ie16 [ENT*D]
__device__ __align__(256) __half g_tabh[(size_t)(MAXU + MAXENT) * 2 * D];
// per-edge relation_ui in fp16
__device__ __align__(256) __half g_rel[(size_t)MAXE * D];
// accumulators: s1 [U*3*D], u2 [U*3*D], ysum [ENT*D], y2 [ENT*D], cnt [U*3], cnti [ENT]
__device__ __align__(256) float g_acc[(size_t)MAXU * NF * D * 2 + (size_t)MAXENT * D * 2
                                      + (size_t)MAXU * NF + MAXENT];
__device__ __align__(256) unsigned char g_rtype[MAXE];

// ---------------- helpers ----------------
__device__ __forceinline__ ull pk2(float a, float b) {
    ull r; asm("mov.b64 %0, {%1, %2};" : "=l"(r) : "f"(a), "f"(b)); return r;
}
__device__ __forceinline__ void fma2(ull& d, ull a, ull b) {
    asm("fma.rn.f32x2 %0, %1, %2, %0;" : "+l"(d) : "l"(a), "l"(b));
}
__device__ __forceinline__ float2 upk2(ull v) {
    float2 f; asm("mov.b64 {%0, %1}, %2;" : "=f"(f.x), "=f"(f.y) : "l"(v)); return f;
}
__device__ __forceinline__ float lrelu(float x) { return x > 0.f ? x : 0.01f * x; }

__device__ __forceinline__ float hsum16(float v) {
    v += __shfl_xor_sync(0xffffffffu, v, 8);
    v += __shfl_xor_sync(0xffffffffu, v, 4);
    v += __shfl_xor_sync(0xffffffffu, v, 2);
    v += __shfl_xor_sync(0xffffffffu, v, 1);
    return v;
}

__device__ __forceinline__ float4 ldh4(const __half* p) {
    uint2 raw = *(const uint2*)p;
    __half2 a = *(__half2*)&raw.x;
    __half2 b = *(__half2*)&raw.y;
    float2 fa = __half22float2(a), fb = __half22float2(b);
    return make_float4(fa.x, fa.y, fb.x, fb.y);
}
__device__ __forceinline__ void sth4(__half* p, float4 v) {
    __half2 h0 = __floats2half2_rn(v.x, v.y);
    __half2 h1 = __floats2half2_rn(v.z, v.w);
    uint2 raw;
    raw.x = *(unsigned int*)&h0;
    raw.y = *(unsigned int*)&h1;
    *(uint2*)p = raw;
}
__device__ __forceinline__ void red4(float* p, float4 v) {
    asm volatile("red.global.add.v4.f32 [%0], {%1, %2, %3, %4};"
                 :: "l"(p), "f"(v.x), "f"(v.y), "f"(v.z), "f"(v.w) : "memory");
}

// ---------------- K0: fused per-source precompute ----------------
// Weights staged in shared (reused by all rows), row x in registers,
// broadcast across the 16-lane group via shfl. One pass per source computes
// BOTH tables (P fp32, Q fp16) plus the fp16 embedding copy.
//  src=user:   P[d] = sum_k WW_w [d][k]      x[k]   Q[d] = sum_k WWi_w[d][64+k] x[k]
//  src=entity: P[d] = sum_k WW_w [d][64+k]   x[k]   Q[d] = sum_k WWi_w[d][k]    x[k]
__global__ __launch_bounds__(256) void precompute2(
    const float* __restrict__ user_emb, const float* __restrict__ entity_emb,
    const float* __restrict__ WW_w, const float* __restrict__ WWi_w,
    float* __restrict__ Pu, float* __restrict__ Pi,
    __half* __restrict__ Qu, __half* __restrict__ Qi,
    __half* __restrict__ ue16, __half* __restrict__ ie16,
    int U, int ENT)
{
    const int role = blockIdx.y;   // 0 = user, 1 = entity
    const float* src; float* Pdst; __half* Qdst; __half* cp; int rows;
    int colA, colB;
    if (role == 0) { src = user_emb;   Pdst = Pu; Qdst = Qu; cp = ue16; rows = U;
                     colA = 0;  colB = D; }
    else           { src = entity_emb; Pdst = Pi; Qdst = Qi; cp = ie16; rows = ENT;
                     colA = D;  colB = 0; }

    __shared__ float wA[D * D];   // wA[k*64 + d] = WW_w [d][colA + k]
    __shared__ float wB[D * D];   // wB[k*64 + d] = WWi_w[d][colB + k]
    for (int idx = threadIdx.x; idx < D * D; idx += 256) {
        int d = idx >> 6, k = idx & 63;
        wA[k * D + d] = WW_w [d * 2 * D + colA + k];
        wB[k * D + d] = WWi_w[d * 2 * D + colB + k];
    }
    __syncthreads();

    const int hw  = blockIdx.x * 16 + (threadIdx.x >> 4);
    const int nhw = gridDim.x * 16;
    const int l16 = threadIdx.x & 15;
    const int d0  = l16 * 4;

    for (int r = hw; r < rows; r += nhw) {
        float4 x = *(const float4*)(src + (size_t)r * D + d0);
        sth4(cp + (size_t)r * D + d0, x);

        ull aA01 = pk2(0.f, 0.f), aA23 = pk2(0.f, 0.f);
        ull aB01 = pk2(0.f, 0.f), aB23 = pk2(0.f, 0.f);

        #pragma unroll
        for (int j = 0; j < 16; j++) {
            float bx = __shfl_sync(0xffffffffu, x.x, j, 16);
            float by = __shfl_sync(0xffffffffu, x.y, j, 16);
            float bz = __shfl_sync(0xffffffffu, x.z, j, 16);
            float bw = __shfl_sync(0xffffffffu, x.w, j, 16);
            float xv[4] = {bx, by, bz, bw};
            #pragma unroll
            for (int kk = 0; kk < 4; kk++) {
                int k = j * 4 + kk;
                float4 wa = *(const float4*)&wA[k * D + d0];
                float4 wb = *(const float4*)&wB[k * D + d0];
                ull xp = pk2(xv[kk], xv[kk]);
                fma2(aA01, pk2(wa.x, wa.y), xp);
                fma2(aA23, pk2(wa.z, wa.w), xp);
                fma2(aB01, pk2(wb.x, wb.y), xp);
                fma2(aB23, pk2(wb.z, wb.w), xp);
            }
        }

        float2 A01 = upk2(aA01), A23 = upk2(aA23);
        *(float4*)(Pdst + (size_t)r * D + d0)
            = make_float4(A01.x, A01.y, A23.x, A23.y);
        float2 B01 = upk2(aB01), B23 = upk2(aB23);
        sth4(Qdst + (size_t)r * D + d0,
             make_float4(B01.x, B01.y, B23.x, B23.y));
    }
}

// ---------------- K1: edge pass 1 — 2 edges per half-warp (MLP) ----------------
__global__ __launch_bounds__(256) void edge_pass1(
    const int* __restrict__ uidx, const int* __restrict__ iidx,
    const float* __restrict__ WW_b, const float* __restrict__ latent,
    const float* __restrict__ Pu, const float* __restrict__ Pi,
    const __half* __restrict__ ue16, const __half* __restrict__ ie16,
    float* __restrict__ s1, float* __restrict__ cnt,
    float* __restrict__ ysum, float* __restrict__ cnti,
    __half* __restrict__ rel_e, unsigned char* __restrict__ rtype, int E)
{
    int p = (blockIdx.x * blockDim.x + threadIdx.x) >> 4;
    int l16 = threadIdx.x & 15;
    int np = (gridDim.x * blockDim.x) >> 4;
    int d0 = l16 * 4;

    float4 bb = *(const float4*)(WW_b + d0);
    float4 l0 = *(const float4*)(latent + 0 * D + d0);
    float4 l1 = *(const float4*)(latent + 1 * D + d0);
    float4 l2 = *(const float4*)(latent + 2 * D + d0);

    for (int e0 = p * 2; e0 < E; e0 += np * 2) {
        int e1 = e0 + 1;
        bool has1 = (e1 < E);
        int u0 = __ldg(uidx + e0), i0 = __ldg(iidx + e0);
        int u1 = has1 ? __ldg(uidx + e1) : u0;
        int i1 = has1 ? __ldg(iidx + e1) : i0;

        float4 pu0 = *(const float4*)(Pu + (size_t)u0 * D + d0);
        float4 pi0 = *(const float4*)(Pi + (size_t)i0 * D + d0);
        float4 pu1 = *(const float4*)(Pu + (size_t)u1 * D + d0);
        float4 pi1 = *(const float4*)(Pi + (size_t)i1 * D + d0);
        float4 ie0 = ldh4(ie16 + (size_t)i0 * D + d0);
        float4 ue0 = ldh4(ue16 + (size_t)u0 * D + d0);
        float4 ie1 = ldh4(ie16 + (size_t)i1 * D + d0);
        float4 ue1 = ldh4(ue16 + (size_t)u1 * D + d0);

        float4 r0;
        r0.x = lrelu(pu0.x + pi0.x + bb.x);
        r0.y = lrelu(pu0.y + pi0.y + bb.y);
        r0.z = lrelu(pu0.z + pi0.z + bb.z);
        r0.w = lrelu(pu0.w + pi0.w + bb.w);
        float a0 = hsum16(r0.x * l0.x + r0.y * l0.y + r0.z * l0.z + r0.w * l0.w);
        float a1 = hsum16(r0.x * l1.x + r0.y * l1.y + r0.z * l1.z + r0.w * l1.w);
        float a2 = hsum16(r0.x * l2.x + r0.y * l2.y + r0.z * l2.z + r0.w * l2.w);
        int t0 = 0; float best0 = a0;
        if (a1 > best0) { best0 = a1; t0 = 1; }
        if (a2 > best0) { best0 = a2; t0 = 2; }

        float4 r1;
        r1.x = lrelu(pu1.x + pi1.x + bb.x);
        r1.y = lrelu(pu1.y + pi1.y + bb.y);
        r1.z = lrelu(pu1.z + pi1.z + bb.z);
        r1.w = lrelu(pu1.w + pi1.w + bb.w);
        float b0 = hsum16(r1.x * l0.x + r1.y * l0.y + r1.z * l0.z + r1.w * l0.w);
        float b1 = hsum16(r1.x * l1.x + r1.y * l1.y + r1.z * l1.z + r1.w * l1.w);
        float b2 = hsum16(r1.x * l2.x + r1.y * l2.y + r1.z * l2.z + r1.w * l2.w);
        int t1 = 0; float best1 = b0;
        if (b1 > best1) { best1 = b1; t1 = 1; }
        if (b2 > best1) { best1 = b2; t1 = 2; }

        sth4(rel_e + (size_t)e0 * D + d0, r0);
        red4(s1 + ((size_t)u0 * NF + t0) * D + d0, ie0);
        red4(ysum + (size_t)i0 * D + d0, ue0);
        if (has1) {
            sth4(rel_e + (size_t)e1 * D + d0, r1);
            red4(s1 + ((size_t)u1 * NF + t1) * D + d0, ie1);
            red4(ysum + (size_t)i1 * D + d0, ue1);
        }
        if (l16 == 0) {
            atomicAdd(cnt + (size_t)u0 * NF + t0, 1.0f);
            atomicAdd(cnti + i0, 1.0f);
            rtype[e0] = (unsigned char)t0;
            if (has1) {
                atomicAdd(cnt + (size_t)u1 * NF + t1, 1.0f);
                atomicAdd(cnti + i1, 1.0f);
                rtype[e1] = (unsigned char)t1;
            }
        }
    }
}

// ---------------- K3: edge pass 2 — 2 edges per half-warp ----------------
__global__ __launch_bounds__(256) void edge_pass2(
    const int* __restrict__ uidx, const int* __restrict__ iidx,
    const float* __restrict__ WWi_b,
    const __half* __restrict__ Qu, const __half* __restrict__ Qi,
    const __half* __restrict__ ue16, const __half* __restrict__ ie16,
    const __half* __restrict__ rel_e, const unsigned char* __restrict__ rtype,
    const float* __restrict__ s1raw, const float* __restrict__ cnt,
    const float* __restrict__ ysraw, const float* __restrict__ cnti,
    float* __restrict__ u2, float* __restrict__ y2, int E)
{
    int p = (blockIdx.x * blockDim.x + threadIdx.x) >> 4;
    int l16 = threadIdx.x & 15;
    int np = (gridDim.x * blockDim.x) >> 4;
    int d0 = l16 * 4;

    float4 bi = *(const float4*)(WWi_b + d0);

    for (int e0 = p * 2; e0 < E; e0 += np * 2) {
        int e1 = e0 + 1;
        bool has1 = (e1 < E);
        int u0 = __ldg(uidx + e0), i0 = __ldg(iidx + e0);
        int u1 = has1 ? __ldg(uidx + e1) : u0;
        int i1 = has1 ? __ldg(iidx + e1) : i0;
        int t0 = rtype[e0];
        int t1 = has1 ? rtype[e1] : t0;

        float4 r0  = ldh4(rel_e + (size_t)e0 * D + d0);
        float4 um0 = *(const float4*)(s1raw + ((size_t)u0 * NF + t0) * D + d0);
        float4 ie0 = ldh4(ie16 + (size_t)i0 * D + d0);
        float4 qi0 = ldh4(Qi + (size_t)i0 * D + d0);
        float4 qu0 = ldh4(Qu + (size_t)u0 * D + d0);
        float4 ym0 = *(const float4*)(ysraw + (size_t)i0 * D + d0);
        float4 ue0 = ldh4(ue16 + (size_t)u0 * D + d0);
        float  c0  = __ldg(cnt + (size_t)u0 * NF + t0);
        float  ci0 = __ldg(cnti + i0);

        float4 r1  = ldh4(rel_e + (size_t)e1 * D * (has1 ? 1 : 0) + d0);
        float4 um1 = *(const float4*)(s1raw + ((size_t)u1 * NF + t1) * D + d0);
        float4 ie1 = ldh4(ie16 + (size_t)i1 * D + d0);
        float4 qi1 = ldh4(Qi + (size_t)i1 * D + d0);
        float4 qu1 = ldh4(Qu + (size_t)u1 * D + d0);
        float4 ym1 = *(const float4*)(ysraw + (size_t)i1 * D + d0);
        float4 ue1 = ldh4(ue16 + (size_t)u1 * D + d0);
        float  c1  = has1 ? __ldg(cnt + (size_t)u1 * NF + t1) : 1.f;
        float  ci1 = has1 ? __ldg(cnti + i1) : 1.f;

        float sim0 = hsum16(r0.x * um0.x + r0.y * um0.y + r0.z * um0.z + r0.w * um0.w)
                   / fmaxf(c0, 1.0f);
        red4(u2 + ((size_t)u0 * NF + t0) * D + d0,
             make_float4(sim0 * ie0.x, sim0 * ie0.y, sim0 * ie0.z, sim0 * ie0.w));

        float4 rr0;
        rr0.x = lrelu(qi0.x + qu0.x + bi.x);
        rr0.y = lrelu(qi0.y + qu0.y + bi.y);
        rr0.z = lrelu(qi0.z + qu0.z + bi.z);
        rr0.w = lrelu(qi0.w + qu0.w + bi.w);
        float simi0 = hsum16(rr0.x * ym0.x + rr0.y * ym0.y + rr0.z * ym0.z + rr0.w * ym0.w)
                    / fmaxf(ci0, 1.0f);
        red4(y2 + (size_t)i0 * D + d0,
             make_float4(simi0 * ue0.x, simi0 * ue0.y, simi0 * ue0.z, simi0 * ue0.w));

        if (has1) {
            float sim1 = hsum16(r1.x * um1.x + r1.y * um1.y + r1.z * um1.z + r1.w * um1.w)
                       / fmaxf(c1, 1.0f);
            red4(u2 + ((size_t)u1 * NF + t1) * D + d0,
                 make_float4(sim1 * ie1.x, sim1 * ie1.y, sim1 * ie1.z, sim1 * ie1.w));

            float4 rr1;
            rr1.x = lrelu(qi1.x + qu1.x + bi.x);
            rr1.y = lrelu(qi1.y + qu1.y + bi.y);
            rr1.z = lrelu(qi1.z + qu1.z + bi.z);
            rr1.w = lrelu(qi1.w + qu1.w + bi.w);
            float simi1 = hsum16(rr1.x * ym1.x + rr1.y * ym1.y + rr1.z * ym1.z + rr1.w * ym1.w)
                        / fmaxf(ci1, 1.0f);
            red4(y2 + (size_t)i1 * D + d0,
                 make_float4(simi1 * ue1.x, simi1 * ue1.y, simi1 * ue1.z, simi1 * ue1.w));
        }
    }
}

// ---------------- K4: squash + residual + combine ----------------
__global__ __launch_bounds__(256) void finalize_entity(
    const float* __restrict__ y2, const float* __restrict__ cnti,
    const float* __restrict__ entity_emb, float* __restrict__ out, int ENT)
{
    int g = blockIdx.x * blockDim.x + threadIdx.x;
    int row = g >> 4;
    int l16 = threadIdx.x & 15;
    int nrows = (gridDim.x * blockDim.x) >> 4;
    int d0 = l16 * 4;
    for (; row < ENT; row += nrows) {
        float inv = 1.0f / fmaxf(cnti[row], 1.0f);
        float4 v = *(const float4*)(y2 + (size_t)row * D + d0);
        v.x *= inv; v.y *= inv; v.z *= inv; v.w *= inv;
        float n2 = hsum16(v.x * v.x + v.y * v.y + v.z * v.z + v.w * v.w);
        float norm = sqrtf(n2);
        float scale = (n2 / (n2 + 1.0f)) / fmaxf(norm, 1e-12f);
        float4 ee = *(const float4*)(entity_emb + (size_t)row * D + d0);
        float4 o;
        o.x = fmaf(scale, v.x, ee.x);
        o.y = fmaf(scale, v.y, ee.y);
        o.z = fmaf(scale, v.z, ee.z);
        o.w = fmaf(scale, v.w, ee.w);
        *(float4*)(out + (size_t)row * D + d0) = o;
    }
}

__global__ __launch_bounds__(256) void finalize_user(
    const float* __restrict__ u2, const float* __restrict__ cnt,
    const float* __restrict__ user_emb, const float* __restrict__ w,
    float* __restrict__ out, int U)
{
    int g = blockIdx.x * blockDim.x + threadIdx.x;
    int row = g >> 4;
    int l16 = threadIdx.x & 15;
    int nrows = (gridDim.x * blockDim.x) >> 4;
    int d0 = l16 * 4;

    float w0 = w[0], w1 = w[1], w2 = w[2];
    float m = fmaxf(w0, fmaxf(w1, w2));
    float e0 = expf(w0 - m), e1 = expf(w1 - m), e2 = expf(w2 - m);
    float inv3 = 1.0f / (e0 + e1 + e2);
    float ws[NF] = {e0 * inv3, e1 * inv3, e2 * inv3};

    for (; row < U; row += nrows) {
        float4 ue = *(const float4*)(user_emb + (size_t)row * D + d0);
        float4 a = make_float4(0.f, 0.f, 0.f, 0.f);
        #pragma unroll
        for (int f = 0; f < NF; f++) {
            float inv = 1.0f / fmaxf(cnt[(size_t)row * NF + f], 1.0f);
            float4 v = *(const float4*)(u2 + ((size_t)row * NF + f) * D + d0);
            v.x *= inv; v.y *= inv; v.z *= inv; v.w *= inv;
            float n2 = hsum16(v.x * v.x + v.y * v.y + v.z * v.z + v.w * v.w);
            float norm = sqrtf(n2);
            float scale = (n2 / (n2 + 1.0f)) / fmaxf(norm, 1e-12f);
            a.x += ws[f] * fmaf(scale, v.x, ue.x);
            a.y += ws[f] * fmaf(scale, v.y, ue.y);
            a.z += ws[f] * fmaf(scale, v.z, ue.z);
            a.w += ws[f] * fmaf(scale, v.w, ue.w);
        }
        *(float4*)(out + (size_t)row * D + d0) = a;
    }
}

// ---------------- host launcher ----------------
extern "C" void kernel_launch(void* const* d_in, const int* in_sizes, int n_in,
                              void* d_out, int out_size)
{
    const float* entity_emb = (const float*)d_in[0];
    const float* user_emb   = (const float*)d_in[1];
    const float* latent     = (const float*)d_in[2];
    const int*   uidx       = (const int*)d_in[3];
    const int*   iidx       = (const int*)d_in[4];
    const float* WW_w       = (const float*)d_in[5];
    const float* WW_b       = (const float*)d_in[6];
    const float* WWi_w      = (const float*)d_in[7];
    const float* WWi_b      = (const float*)d_in[8];
    const float* w          = (const float*)d_in[9];

    int ENT = in_sizes[0] / D;
    int U   = in_sizes[1] / D;
    int E   = in_sizes[3];

    float* out = (float*)d_out;

    float* tabf; __half* tabh; __half* rel; float* acc; unsigned char* rt;
    cudaGetSymbolAddress((void**)&tabf, g_tabf);
    cudaGetSymbolAddress((void**)&tabh, g_tabh);
    cudaGetSymbolAddress((void**)&rel,  g_rel);
    cudaGetSymbolAddress((void**)&acc,  g_acc);
    cudaGetSymbolAddress((void**)&rt,   g_rtype);

    float* Pu = tabf;
    float* Pi = Pu + (size_t)U * D;
    __half* Qu   = tabh;
    __half* Qi   = Qu + (size_t)U * D;
    __half* ue16 = Qi + (size_t)ENT * D;
    __half* ie16 = ue16 + (size_t)U * D;

    float* s1   = acc;
    float* u2   = s1 + (size_t)U * NF * D;
    float* ys   = u2 + (size_t)U * NF * D;
    float* y2   = ys + (size_t)ENT * D;
    float* cnt  = y2 + (size_t)ENT * D;
    float* cnti = cnt + (size_t)U * NF;
    size_t accN = (size_t)U * NF * D * 2 + (size_t)ENT * D * 2 + (size_t)U * NF + ENT;

    cudaMemsetAsync(acc, 0, accN * sizeof(float));

    precompute2<<<dim3(1024, 2), 256>>>(user_emb, entity_emb, WW_w, WWi_w,
                                        Pu, Pi, Qu, Qi, ue16, ie16, U, ENT);

    int eblocks = (E + 31) / 32;  // 16 half-warps/block × 2 edges each
    edge_pass1<<<eblocks, 256>>>(uidx, iidx, WW_b, latent, Pu, Pi, ue16, ie16,
                                 s1, cnt, ys, cnti, rel, rt, E);

    edge_pass2<<<eblocks, 256>>>(uidx, iidx, WWi_b, Qu, Qi, ue16, ie16, rel, rt,
                                 s1, cnt, ys, cnti, u2, y2, E);

    finalize_entity<<<(ENT * 16 + 255) / 256, 256>>>(y2, cnti, entity_emb, out, ENT);
    finalize_user<<<(U * 16 + 255) / 256, 256>>>(u2, cnt, user_emb, w, out + (size_t)ENT * D, U);
}